// round 4
// baseline (speedup 1.0000x reference)
#include <cuda_runtime.h>
#include <cstdint>

#define B_     8
#define NQ_    12544
#define NKV_   12544
#define C_     128
#define H_     112
#define WI_    224
#define NINIT_ 50176
#define NS_    784
#define HS_    28
#define INV4_  (1.0f/(4.0f+1e-06f))

// ---------------- scratch (device globals; allocations are forbidden) ------
static __device__ float g_q  [B_*NQ_*C_];    // q_x @ q_w * SCALE  (col = h*64+d)
static __device__ float g_map[B_*H_*H_*C_];  // kv map, channel-last [b][y][x][c]
static __device__ float g_wt [2048*128];     // sr_w transposed: [(p*128+c)][o]
static __device__ float g_kvr[B_*NS_*C_];    // conv output, token-major
static __device__ float g_k  [B_*2*NS_*64];  // [b][h][s][d]
static __device__ float g_v  [B_*2*NS_*64];
static __device__ float g_conf[B_*NS_];
static __device__ float g_ao [B_*NQ_*C_];    // attention out (col = h*64+d)

// ---------------- sr_w transpose: [o][c][ky][kx] -> [(p*128+c)][o] ----------
__global__ void k_wt(const float* __restrict__ srw){
    int idx = blockIdx.x * blockDim.x + threadIdx.x;
    if (idx >= 2048*128) return;
    int p = idx & 15, c = (idx >> 4) & 127, o = idx >> 11;
    g_wt[(p*128 + c)*128 + o] = srw[idx];
}

// ---------------- token2map: each map cell = avg of 4 gathered tokens ------
__global__ __launch_bounds__(128) void k_t2m(const float* __restrict__ kvx,
                                             const int* __restrict__ idx){
    int warp = threadIdx.x >> 5, lane = threadIdx.x & 31;
    int cell = blockIdx.x * 4 + warp;          // = b*12544 + y*112 + x
    int b  = cell / (H_*H_);
    int yx = cell % (H_*H_);
    int y = yx / H_, x = yx % H_;
    const int* ib = idx + (size_t)b*NINIT_ + (2*y)*WI_ + 2*x;
    int i0 = ib[0], i1 = ib[1], i2 = ib[WI_], i3 = ib[WI_+1];
    const float* base = kvx + (size_t)b*NKV_*C_;
    int c4 = lane * 4;
    float4 a = *(const float4*)(base + (size_t)i0*C_ + c4);
    float4 bb= *(const float4*)(base + (size_t)i1*C_ + c4);
    float4 cc= *(const float4*)(base + (size_t)i2*C_ + c4);
    float4 dd= *(const float4*)(base + (size_t)i3*C_ + c4);
    float4 o;
    o.x = (a.x+bb.x+cc.x+dd.x)*INV4_;
    o.y = (a.y+bb.y+cc.y+dd.y)*INV4_;
    o.z = (a.z+bb.z+cc.z+dd.z)*INV4_;
    o.w = (a.w+bb.w+cc.w+dd.w)*INV4_;
    *(float4*)(g_map + (size_t)cell*C_ + c4) = o;
}

// ---------------- conf: pooled token_score over the 8x8 init block ----------
__global__ __launch_bounds__(128) void k_conf(const float* __restrict__ score,
                                              const int* __restrict__ idx){
    int warp = threadIdx.x >> 5, lane = threadIdx.x & 31;
    int sidx = blockIdx.x * 4 + warp;           // < B_*NS_
    int b = sidx / NS_, s = sidx % NS_;
    int ii = s / HS_, jj = s % HS_;
    const int* ib = idx + (size_t)b*NINIT_;
    float sum = 0.f;
#pragma unroll
    for (int rep = 0; rep < 2; rep++){
        int p = lane + rep*32;                  // 0..63 within 8x8 block
        int rr = p >> 3, cc = p & 7;
        int tok = ib[(8*ii + rr)*WI_ + 8*jj + cc];
        sum += score[(size_t)b*NKV_ + tok];
    }
#pragma unroll
    for (int off = 16; off >= 1; off >>= 1)
        sum += __shfl_xor_sync(0xffffffffu, sum, off);
    if (lane == 0) g_conf[sidx] = sum * (INV4_ * (1.0f/16.0f));
}

// ---------------- generic Mx128 @ 128x128 GEMM, 64-row tiles ----------------
__device__ __forceinline__ void gemm128_body(const float* __restrict__ A,
                                             const float* __restrict__ W,
                                             const float* __restrict__ bias,
                                             float alpha, float* __restrict__ Cout){
    __shared__ __align__(16) float sA[32*64];   // [k][m]
    __shared__ __align__(16) float sW[32*128];  // [k][n]
    int t  = threadIdx.x;
    int tx = t & 15, ty = t >> 4;
    size_t m0 = (size_t)blockIdx.x * 64;
    int lr = t >> 2, lc = (t & 3) * 8;
    float acc[4][8];
#pragma unroll
    for (int i = 0; i < 4; i++)
#pragma unroll
        for (int j = 0; j < 8; j++) acc[i][j] = 0.f;

    for (int q = 0; q < 4; q++){
        __syncthreads();
        const float* ap = A + (m0 + lr)*128 + q*32 + lc;
        float4 a0 = *(const float4*)ap;
        float4 a1 = *(const float4*)(ap + 4);
        sA[(lc+0)*64+lr]=a0.x; sA[(lc+1)*64+lr]=a0.y; sA[(lc+2)*64+lr]=a0.z; sA[(lc+3)*64+lr]=a0.w;
        sA[(lc+4)*64+lr]=a1.x; sA[(lc+5)*64+lr]=a1.y; sA[(lc+6)*64+lr]=a1.z; sA[(lc+7)*64+lr]=a1.w;
#pragma unroll
        for (int u = 0; u < 4; u++){
            int pos = u*256 + t; int kk = pos >> 5; int c4 = (pos & 31)*4;
            *(float4*)(sW + kk*128 + c4) = *(const float4*)(W + (size_t)(q*32+kk)*128 + c4);
        }
        __syncthreads();
#pragma unroll
        for (int kk = 0; kk < 32; kk++){
            float4 av = *(const float4*)(sA + kk*64 + ty*4);
            float4 w0 = *(const float4*)(sW + kk*128 + tx*8);
            float4 w1 = *(const float4*)(sW + kk*128 + tx*8 + 4);
            float a[4] = {av.x, av.y, av.z, av.w};
            float w[8] = {w0.x,w0.y,w0.z,w0.w,w1.x,w1.y,w1.z,w1.w};
#pragma unroll
            for (int i = 0; i < 4; i++)
#pragma unroll
                for (int j = 0; j < 8; j++) acc[i][j] += a[i]*w[j];
        }
    }
#pragma unroll
    for (int i = 0; i < 4; i++){
        size_t m = m0 + ty*4 + i;
        float* cp = Cout + m*128 + tx*8;
        float4 o0, o1;
        o0.x = acc[i][0]*alpha + (bias ? bias[tx*8+0] : 0.f);
        o0.y = acc[i][1]*alpha + (bias ? bias[tx*8+1] : 0.f);
        o0.z = acc[i][2]*alpha + (bias ? bias[tx*8+2] : 0.f);
        o0.w = acc[i][3]*alpha + (bias ? bias[tx*8+3] : 0.f);
        o1.x = acc[i][4]*alpha + (bias ? bias[tx*8+4] : 0.f);
        o1.y = acc[i][5]*alpha + (bias ? bias[tx*8+5] : 0.f);
        o1.z = acc[i][6]*alpha + (bias ? bias[tx*8+6] : 0.f);
        o1.w = acc[i][7]*alpha + (bias ? bias[tx*8+7] : 0.f);
        *(float4*)cp       = o0;
        *(float4*)(cp + 4) = o1;
    }
}

__global__ __launch_bounds__(256) void k_qproj(const float* __restrict__ A,
                                               const float* __restrict__ W){
    gemm128_body(A, W, nullptr, 0.125f, g_q);   // SCALE = 64^-0.5 folded in
}
__global__ __launch_bounds__(256) void k_oproj(const float* __restrict__ W,
                                               const float* __restrict__ bias,
                                               float* __restrict__ out){
    gemm128_body(g_ao, W, bias, 1.0f, out);
}

// ---------------- conv as GEMM: [6272 x 2048] @ [2048 x 128] ----------------
__global__ __launch_bounds__(256) void k_conv(const float* __restrict__ bias){
    __shared__ __align__(16) float sA[32*64];
    __shared__ __align__(16) float sW[32*128];
    int t  = threadIdx.x;
    int tx = t & 15, ty = t >> 4;
    int m0 = blockIdx.x * 64;
    int lr = t >> 2, lc = (t & 3) * 8;
    int m  = m0 + lr;
    int b  = m / NS_; int s = m % NS_;
    int ii = s / HS_, jj = s % HS_;
    size_t base0 = (((size_t)b*H_ + 4*ii)*H_ + 4*jj)*C_;
    float acc[4][8];
#pragma unroll
    for (int i = 0; i < 4; i++)
#pragma unroll
        for (int j = 0; j < 8; j++) acc[i][j] = 0.f;

    for (int q = 0; q < 64; q++){
        int p  = q >> 2;            // patch cell 0..15 (ky*4+kx)
        int c0 = (q & 3) * 32;      // channel offset
        int ky = p >> 2, kx = p & 3;
        __syncthreads();
        const float* ap = g_map + base0 + (size_t)(ky*H_ + kx)*C_ + c0 + lc;
        float4 a0 = *(const float4*)ap;
        float4 a1 = *(const float4*)(ap + 4);
        sA[(lc+0)*64+lr]=a0.x; sA[(lc+1)*64+lr]=a0.y; sA[(lc+2)*64+lr]=a0.z; sA[(lc+3)*64+lr]=a0.w;
        sA[(lc+4)*64+lr]=a1.x; sA[(lc+5)*64+lr]=a1.y; sA[(lc+6)*64+lr]=a1.z; sA[(lc+7)*64+lr]=a1.w;
        const float* wp = g_wt + (size_t)q*32*128;
#pragma unroll
        for (int u = 0; u < 4; u++){
            int pos = u*256 + t; int kk = pos >> 5; int c4 = (pos & 31)*4;
            *(float4*)(sW + kk*128 + c4) = *(const float4*)(wp + kk*128 + c4);
        }
        __syncthreads();
#pragma unroll
        for (int kk = 0; kk < 32; kk++){
            float4 av = *(const float4*)(sA + kk*64 + ty*4);
            float4 w0 = *(const float4*)(sW + kk*128 + tx*8);
            float4 w1 = *(const float4*)(sW + kk*128 + tx*8 + 4);
            float a[4] = {av.x, av.y, av.z, av.w};
            float w[8] = {w0.x,w0.y,w0.z,w0.w,w1.x,w1.y,w1.z,w1.w};
#pragma unroll
            for (int i = 0; i < 4; i++)
#pragma unroll
                for (int j = 0; j < 8; j++) acc[i][j] += a[i]*w[j];
        }
    }
#pragma unroll
    for (int i = 0; i < 4; i++){
        size_t mm = (size_t)m0 + ty*4 + i;
        float* cp = g_kvr + mm*128 + tx*8;
        float4 o0, o1;
        o0.x = acc[i][0] + bias[tx*8+0]; o0.y = acc[i][1] + bias[tx*8+1];
        o0.z = acc[i][2] + bias[tx*8+2]; o0.w = acc[i][3] + bias[tx*8+3];
        o1.x = acc[i][4] + bias[tx*8+4]; o1.y = acc[i][5] + bias[tx*8+5];
        o1.z = acc[i][6] + bias[tx*8+6]; o1.w = acc[i][7] + bias[tx*8+7];
        *(float4*)cp       = o0;
        *(float4*)(cp + 4) = o1;
    }
}

// ---------------- LayerNorm + kv projection (16 rows / block) ---------------
__global__ __launch_bounds__(256) void k_lnkv(const float* __restrict__ kvw,
                                              const float* __restrict__ gamma,
                                              const float* __restrict__ beta){
    __shared__ __align__(16) float sY[16*128];
    int t = threadIdx.x; int warp = t >> 5, lane = t & 31;
    int row0 = blockIdx.x * 16;
#pragma unroll
    for (int rr = 0; rr < 2; rr++){
        int r = warp*2 + rr;
        size_t grow = (size_t)row0 + r;
        const float* xp = g_kvr + grow*128 + lane*4;
        float4 xv = *(const float4*)xp;
        float s1 = xv.x + xv.y + xv.z + xv.w;
        float s2 = xv.x*xv.x + xv.y*xv.y + xv.z*xv.z + xv.w*xv.w;
#pragma unroll
        for (int off = 16; off >= 1; off >>= 1){
            s1 += __shfl_xor_sync(0xffffffffu, s1, off);
            s2 += __shfl_xor_sync(0xffffffffu, s2, off);
        }
        float mean = s1 * (1.0f/128.0f);
        float var  = s2 * (1.0f/128.0f) - mean*mean;
        float rstd = rsqrtf(var + 1e-5f);
        int c = lane * 4;
        float4 gv = *(const float4*)(gamma + c);
        float4 bv = *(const float4*)(beta  + c);
        float4 y;
        y.x = (xv.x - mean)*rstd*gv.x + bv.x;
        y.y = (xv.y - mean)*rstd*gv.y + bv.y;
        y.z = (xv.z - mean)*rstd*gv.z + bv.z;
        y.w = (xv.w - mean)*rstd*gv.w + bv.w;
        *(float4*)(sY + r*128 + c) = y;
    }
    __syncthreads();
    // Y[16x128] @ kvw[128x256]; thread t owns column c = t
    int c = t;
    float acc[16];
#pragma unroll
    for (int r = 0; r < 16; r++) acc[r] = 0.f;
    for (int kk = 0; kk < 128; kk++){
        float w = kvw[(size_t)kk*256 + c];
#pragma unroll
        for (int r = 0; r < 16; r++) acc[r] += sY[r*128 + kk] * w;
    }
    int kvsel = c >> 7, rem = c & 127;
    int h = rem >> 6, d = rem & 63;
    float* dst = kvsel ? g_v : g_k;
#pragma unroll
    for (int r = 0; r < 16; r++){
        int grow = row0 + r;                    // = b*784 + s
        int b = grow / NS_, s = grow % NS_;
        dst[((size_t)(b*2 + h)*NS_ + s)*64 + d] = acc[r];
    }
}

// ---------------- flash attention: 64 queries x 1 head per block ------------
#define SMEM_ATTN_BYTES ((64*64 + 64*128 + 128*64 + 128)*4)
__global__ __launch_bounds__(256, 2) void k_attn(){
    extern __shared__ float sm[];
    float* sQ  = sm;             // [d][q] 64x64
    float* sKT = sQ + 64*64;     // [d][k] 64x128  (aliased by P [q][k] later)
    float* sV  = sKT + 64*128;   // [k][d] 128x64
    float* sC  = sV + 128*64;    // [128]
    int t = threadIdx.x;
    int qt = blockIdx.x, h = blockIdx.y, b = blockIdx.z;
    int tx = t & 15, ty = t >> 4;
    {   // load Q tile transposed
        int lr = t >> 2, lc = (t & 3) * 16;
        const float* gp = g_q + ((size_t)(b*NQ_ + qt*64 + lr))*128 + h*64 + lc;
#pragma unroll
        for (int j = 0; j < 4; j++){
            float4 v = *(const float4*)(gp + j*4);
            sQ[(lc + j*4 + 0)*64 + lr] = v.x;
            sQ[(lc + j*4 + 1)*64 + lr] = v.y;
            sQ[(lc + j*4 + 2)*64 + lr] = v.z;
            sQ[(lc + j*4 + 3)*64 + lr] = v.w;
        }
    }
    float m[4], l[4], o[4][4];
#pragma unroll
    for (int i = 0; i < 4; i++){
        m[i] = -1e30f; l[i] = 0.f;
#pragma unroll
        for (int j = 0; j < 4; j++) o[i][j] = 0.f;
    }
    const float* Kbase = g_k + (size_t)(b*2+h)*NS_*64;
    const float* Vbase = g_v + (size_t)(b*2+h)*NS_*64;

    for (int ch = 0; ch < 7; ch++){
        int k0 = ch*128;
        int nvalid = NS_ - k0; if (nvalid > 128) nvalid = 128;
        __syncthreads();                       // prior PV reads done
        {   // load K^T (scatter) and V (copy); zero-pad invalid keys
            int kk = t >> 1, dc = (t & 1)*32;
            if (kk < nvalid){
                const float* kp = Kbase + (size_t)(k0+kk)*64 + dc;
#pragma unroll
                for (int j = 0; j < 8; j++){
                    float4 v = *(const float4*)(kp + j*4);
                    sKT[(dc+j*4+0)*128 + kk] = v.x;
                    sKT[(dc+j*4+1)*128 + kk] = v.y;
                    sKT[(dc+j*4+2)*128 + kk] = v.z;
                    sKT[(dc+j*4+3)*128 + kk] = v.w;
                }
                const float* vp = Vbase + (size_t)(k0+kk)*64 + dc;
                float4* sv = (float4*)(sV + kk*64 + dc);
#pragma unroll
                for (int j = 0; j < 8; j++) sv[j] = *(const float4*)(vp + j*4);
            } else {
#pragma unroll
                for (int j = 0; j < 8; j++){
                    sKT[(dc+j*4+0)*128+kk]=0.f; sKT[(dc+j*4+1)*128+kk]=0.f;
                    sKT[(dc+j*4+2)*128+kk]=0.f; sKT[(dc+j*4+3)*128+kk]=0.f;
                }
                float4 z = make_float4(0.f,0.f,0.f,0.f);
                float4* sv = (float4*)(sV + kk*64 + dc);
#pragma unroll
                for (int j = 0; j < 8; j++) sv[j] = z;
            }
            if (t < 128) sC[t] = (k0 + t < NS_) ? g_conf[b*NS_ + k0 + t] : 0.f;
        }
        __syncthreads();
        // S = Q @ K^T  (thread tile 4q x 8k)
        float acc[4][8];
#pragma unroll
        for (int i = 0; i < 4; i++)
#pragma unroll
            for (int j = 0; j < 8; j++) acc[i][j] = 0.f;
        for (int d = 0; d < 64; d++){
            float4 qv = *(const float4*)(sQ  + d*64  + ty*4);
            float4 ka = *(const float4*)(sKT + d*128 + tx*8);
            float4 kb = *(const float4*)(sKT + d*128 + tx*8 + 4);
            float qa[4] = {qv.x, qv.y, qv.z, qv.w};
            float kv8[8] = {ka.x,ka.y,ka.z,ka.w,kb.x,kb.y,kb.z,kb.w};
#pragma unroll
            for (int i = 0; i < 4; i++)
#pragma unroll
                for (int j = 0; j < 8; j++) acc[i][j] += qa[i]*kv8[j];
        }
        // online softmax (conf bias + tail mask)
#pragma unroll
        for (int i = 0; i < 4; i++){
            float rm = -1e30f;
#pragma unroll
            for (int j = 0; j < 8; j++){
                int kg = k0 + tx*8 + j;
                float s = (kg < NS_) ? (acc[i][j] + sC[tx*8+j]) : -1e30f;
                acc[i][j] = s;
                rm = fmaxf(rm, s);
            }
#pragma unroll
            for (int off = 8; off >= 1; off >>= 1)
                rm = fmaxf(rm, __shfl_xor_sync(0xffffffffu, rm, off, 16));
            float mn = fmaxf(m[i], rm);
            float sc = __expf(m[i] - mn);
            float rs = 0.f;
#pragma unroll
            for (int j = 0; j < 8; j++){
                float p = __expf(acc[i][j] - mn);
                acc[i][j] = p;
                rs += p;
            }
#pragma unroll
            for (int off = 8; off >= 1; off >>= 1)
                rs += __shfl_xor_sync(0xffffffffu, rs, off, 16);
            l[i] = l[i]*sc + rs;
            m[i] = mn;
#pragma unroll
            for (int j = 0; j < 4; j++) o[i][j] *= sc;
        }
        __syncthreads();                       // everyone done reading sKT
        {   // write P into sKT's space
#pragma unroll
            for (int i = 0; i < 4; i++){
                float4 p0 = make_float4(acc[i][0],acc[i][1],acc[i][2],acc[i][3]);
                float4 p1 = make_float4(acc[i][4],acc[i][5],acc[i][6],acc[i][7]);
                float4* pp = (float4*)(sKT + (ty*4+i)*128 + tx*8);
                pp[0] = p0; pp[1] = p1;
            }
        }
        __syncthreads();
        // O += P @ V  (thread tile 4q x 4d)
        const float* sP = sKT;
#pragma unroll 2
        for (int k = 0; k < 128; k += 4){
            float4 pr[4];
#pragma unroll
            for (int i = 0; i < 4; i++) pr[i] = *(const float4*)(sP + (ty*4+i)*128 + k);
            float4 v0 = *(const float4*)(sV + (k+0)*64 + tx*4);
            float4 v1 = *(const float4*)(sV + (k+1)*64 + tx*4);
            float4 v2 = *(const float4*)(sV + (k+2)*64 + tx*4);
            float4 v3 = *(const float4*)(sV + (k+3)*64 + tx*4);
#pragma unroll
            for (int i = 0; i < 4; i++){
                o[i][0] += pr[i].x*v0.x + pr[i].y*v1.x + pr[i].z*v2.x + pr[i].w*v3.x;
                o[i][1] += pr[i].x*v0.y + pr[i].y*v1.y + pr[i].z*v2.y + pr[i].w*v3.y;
                o[i][2] += pr[i].x*v0.z + pr[i].y*v1.z + pr[i].z*v2.z + pr[i].w*v3.z;
                o[i][3] += pr[i].x*v0.w + pr[i].y*v1.w + pr[i].z*v2.w + pr[i].w*v3.w;
            }
        }
    }
#pragma unroll
    for (int i = 0; i < 4; i++){
        float inv = 1.0f / l[i];
        float4 ov = make_float4(o[i][0]*inv, o[i][1]*inv, o[i][2]*inv, o[i][3]*inv);
        *(float4*)(g_ao + ((size_t)(b*NQ_ + qt*64 + ty*4 + i))*128 + h*64 + tx*4) = ov;
    }
}

// ---------------- host launcher --------------------------------------------
extern "C" void kernel_launch(void* const* d_in, const int* in_sizes, int n_in,
                              void* d_out, int out_size) {
    const float *q_x=0,*kv_x=0,*score=0,*q_w=0,*kv_w=0,*proj_w=0,*proj_b=0,
                *sr_w=0,*sr_b=0,*norm_g=0,*norm_b=0;
    const int* idx = 0;
    int c12m = 0, c16k = 0, c128 = 0;
    for (int i = 0; i < n_in; i++){
        int s = in_sizes[i];
        const void* p = d_in[i];
        if (s == 12845056){ if (c12m++ == 0) q_x = (const float*)p; else kv_x = (const float*)p; }
        else if (s == 100352) score = (const float*)p;
        else if (s == 401408) idx = (const int*)p;
        else if (s == 16384){ if (c16k++ == 0) q_w = (const float*)p; else proj_w = (const float*)p; }
        else if (s == 32768) kv_w = (const float*)p;
        else if (s == 262144) sr_w = (const float*)p;
        else if (s == 128){
            if      (c128 == 0) proj_b = (const float*)p;
            else if (c128 == 1) sr_b   = (const float*)p;
            else if (c128 == 2) norm_g = (const float*)p;
            else                norm_b = (const float*)p;
            c128++;
        }
        // sizes 1 (H, W, H_init, W_init) are fixed constants; ignored
    }

    cudaFuncSetAttribute(k_attn, cudaFuncAttributeMaxDynamicSharedMemorySize,
                         SMEM_ATTN_BYTES);

    k_wt  <<<2048, 128>>>(sr_w);
    k_t2m <<<25088, 128>>>(kv_x, idx);
    k_conf<<<1568, 128>>>(score, idx);
    k_qproj<<<1568, 256>>>(q_x, q_w);
    k_conv<<<98, 256>>>(sr_b);
    k_lnkv<<<392, 256>>>(kv_w, norm_g, norm_b);
    k_attn<<<dim3(196, 2, 8), 256, SMEM_ATTN_BYTES>>>();
    k_oproj<<<1568, 256>>>(proj_w, proj_b, (float*)d_out);
}